// round 15
// baseline (speedup 1.0000x reference)
#include <cuda_runtime.h>
#include <cuda_fp16.h>
#include <cstdint>
#include <cstddef>

#define IN_F   1024
#define OUT_F  1024
#define BATCH  8192
#define NFEAT  7
#define KTOT   (IN_F * NFEAT)   // 7168

// ---------------------------------------------------------------------------
// Scratch: fp16 operands. g_A: [b][k] row-major. g_W: [o][k].
// ---------------------------------------------------------------------------
__device__ __align__(256) __half g_A[(size_t)BATCH * KTOT];
__device__ __align__(256) __half g_W[(size_t)OUT_F * KTOT];

// ---------------------------------------------------------------------------
// Helpers
// ---------------------------------------------------------------------------
__device__ __forceinline__ unsigned smem_u32(const void* p) {
    return (unsigned)__cvta_generic_to_shared(p);
}
#define CP_ASYNC16(dst_u32, src_ptr) \
    asm volatile("cp.async.cg.shared.global [%0], [%1], 16;\n" :: "r"(dst_u32), "l"(src_ptr))
#define CP_COMMIT() asm volatile("cp.async.commit_group;\n")
#define CP_WAIT(n)  asm volatile("cp.async.wait_group %0;\n" :: "n"(n))

#define LDSM_X4(r0, r1, r2, r3, addr) \
    asm volatile("ldmatrix.sync.aligned.m8n8.x4.shared.b16 {%0,%1,%2,%3}, [%4];" \
                 : "=r"(r0), "=r"(r1), "=r"(r2), "=r"(r3) : "r"(addr))

#define MMA_F16(d, a0, a1, a2, a3, b0, b1) \
    asm volatile( \
        "mma.sync.aligned.m16n8k16.row.col.f32.f16.f16.f32 " \
        "{%0,%1,%2,%3}, {%4,%5,%6,%7}, {%8,%9}, {%0,%1,%2,%3};" \
        : "+f"((d)[0]), "+f"((d)[1]), "+f"((d)[2]), "+f"((d)[3]) \
        : "r"(a0), "r"(a1), "r"(a2), "r"(a3), "r"(b0), "r"(b1))

// ---------------------------------------------------------------------------
// Kernel 1: combined prep (one launch, three independent grid partitions).
//   bx <  BATCH             : features for batch row bx -> g_A
//   BATCH <= bx < BATCH+OUT_F : combined weights -> g_W
//   bx >= BATCH+OUT_F       : zero the output C (split-K accumulates into it)
// ---------------------------------------------------------------------------
#define ZB (BATCH + OUT_F)      // zero-partition base
#define NZBLK 256               // 256 blocks x 4 y x 8192 floats = 8M floats

__global__ void kan_prep(const float* __restrict__ x,
                         const float* __restrict__ bw,
                         const float* __restrict__ sw,
                         const float* __restrict__ sc,
                         float* __restrict__ C) {
    int bx = blockIdx.x;
    int tid = threadIdx.x;

    if (bx >= ZB) {
        // zero C: chunk = ((bx-ZB)*4 + by) * 8192 floats
        size_t off = ((size_t)(bx - ZB) * 4 + blockIdx.y) * 8192;
        float4* p = (float4*)(C + off);
        const float4 z = make_float4(0.f, 0.f, 0.f, 0.f);
#pragma unroll
        for (int r = 0; r < 8; r++) p[tid + r * 256] = z;
        return;
    }

    __shared__ __half sbuf[256 * NFEAT];
    int i = blockIdx.y * 256 + tid;
    float vals[NFEAT];

    if (bx < BATCH) {
        float xv = x[(size_t)bx * IN_F + i];
        float tt = xv * xv;
        float P = fmaf(tt, fmaf(tt, fmaf(tt, -2.10813e-4f, 2.08333333e-3f),
                                -2.08333333e-2f), 0.25f);
        vals[0] = xv * fmaf(xv, P, 0.5f);
        float u  = (xv + 1.0f) * 1.5f;
        int idx  = (int)floorf(u);
        idx = idx < 0 ? 0 : (idx > 2 ? 2 : idx);
        float t  = u - (float)idx;
        float t2 = t * t, t3 = t2 * t;
        float omt = 1.0f - t;
        const float c6 = 1.0f / 6.0f;
        float v0 = omt * omt * omt * c6;
        float v1 = (3.0f * t3 - 6.0f * t2 + 4.0f) * c6;
        float v2 = (-3.0f * t3 + 3.0f * t2 + 3.0f * t + 1.0f) * c6;
        float v3 = t3 * c6;
        vals[1] = (idx == 0) ? v0 : 0.0f;
        vals[2] = (idx == 0) ? v1 : ((idx == 1) ? v0 : 0.0f);
        vals[3] = (idx == 0) ? v2 : ((idx == 1) ? v1 : v0);
        vals[4] = (idx == 0) ? v3 : ((idx == 1) ? v2 : v1);
        vals[5] = (idx == 1) ? v3 : ((idx == 2) ? v2 : 0.0f);
        vals[6] = (idx == 2) ? v3 : 0.0f;
    } else {
        int o = bx - BATCH;
        size_t oi = (size_t)o * IN_F + i;
        float s = sc[oi];
        vals[0] = bw[oi];
        const float* swp = sw + oi * 6;
#pragma unroll
        for (int n = 0; n < 6; n++) vals[n + 1] = swp[n] * s;
    }

#pragma unroll
    for (int j = 0; j < NFEAT; j++)
        sbuf[tid * NFEAT + j] = __float2half_rn(vals[j]);
    __syncthreads();

    __half* gdst = (bx < BATCH) ? (g_A + (size_t)bx * KTOT)
                                : (g_W + (size_t)(bx - BATCH) * KTOT);
    float4* dst = (float4*)(gdst + (size_t)blockIdx.y * (256 * NFEAT));
    if (tid < 224) dst[tid] = ((const float4*)sbuf)[tid];
}

// ---------------------------------------------------------------------------
// Kernel 2: fp16 mma.sync GEMM, SPLIT-K x4 vs wave quantization.
// 1024 work units (64 bm x 4 bn x 4 ks), each a full CTA: 128x256 tile over
// K chunk of 1792 (28 BK=64 iters). ceil(1024/148)=7 waves vs 6.92 ideal
// (1.2% tail vs 15.7% with 256 full-K tiles). Partial sums combined with
// fp32 atomicAdd (RED); C pre-zeroed by kan_prep.
// Tile engine identical to R14: 512 thr, 16 warps (4M x 4N, warp 32x64),
// 144B row stride, 3-stage cp.async ring.
// ---------------------------------------------------------------------------
#define BM 128
#define BN 256
#define BK 64
#define KSPLIT 4
#define KCHUNK (KTOT / KSPLIT)  // 1792
#define NTU (KCHUNK / BK)       // 28 iters per unit
#define ROWB 144
#define A_STG_B (BM * ROWB)     // 18432
#define B_STG_B (BN * ROWB)     // 36864
#define STG_B (A_STG_B + B_STG_B)
#define NSTAGE 3
#define SMEM_TOTAL (NSTAGE * STG_B)   // 165888
#define NTHREADS 512

__device__ __forceinline__ void load_stage(uint32_t sb, int bm0, int bn0,
                                           int k0, int stg, int tid) {
    uint32_t base = sb + stg * STG_B;
#pragma unroll
    for (int r = 0; r < 2; r++) {
        int c = tid + r * NTHREADS;
        int row = c >> 3, ch = c & 7;
        CP_ASYNC16(base + (uint32_t)(row * ROWB + ch * 16),
                   g_A + (size_t)(bm0 + row) * KTOT + k0 + ch * 8);
    }
    uint32_t bbase = base + A_STG_B;
#pragma unroll
    for (int r = 0; r < 4; r++) {
        int c = tid + r * NTHREADS;
        int row = c >> 3, ch = c & 7;
        CP_ASYNC16(bbase + (uint32_t)(row * ROWB + ch * 16),
                   g_W + (size_t)(bn0 + row) * KTOT + k0 + ch * 8);
    }
    CP_COMMIT();
}

__global__ __launch_bounds__(NTHREADS, 1) void kan_gemm(float* __restrict__ C) {
    extern __shared__ char dsm[];
    uint32_t sb = smem_u32(dsm);
    const int tid = threadIdx.x;
    const int wid = tid >> 5, lane = tid & 31;
    const int q = lane >> 2, cl = lane & 3;

    // unit decode: unit = bm*16 + ks*4 + bn (consecutive units share A chunk)
    const int unit = blockIdx.x;
    const int bm0 = (unit >> 4) * BM;
    const int ks  = (unit >> 2) & 3;
    const int bn0 = (unit & 3) * BN;
    const int kbase = ks * KCHUNK;

    const int m0 = (wid & 3) * 32;
    const int n0 = (wid >> 2) * 64;

    float d[2][8][4];
#pragma unroll
    for (int mb = 0; mb < 2; mb++)
#pragma unroll
        for (int nb = 0; nb < 8; nb++)
#pragma unroll
            for (int r = 0; r < 4; r++) d[mb][nb][r] = 0.0f;

    load_stage(sb, bm0, bn0, kbase, 0, tid);
    load_stage(sb, bm0, bn0, kbase + BK, 1, tid);

    const int r8 = lane & 7, tq = lane >> 3;
    const uint32_t afoff =
        (uint32_t)((m0 + (tq & 1) * 8 + r8) * ROWB + (tq >> 1) * 16);
    const uint32_t bfoff =
        (uint32_t)(A_STG_B + (n0 + (tq >> 1) * 8 + r8) * ROWB + (tq & 1) * 16);

    for (int t = 0; t < NTU; t++) {
        const int stg = t % NSTAGE;
        CP_WAIT(1);
        __syncthreads();
        if (t + 2 < NTU)
            load_stage(sb, bm0, bn0, kbase + (t + 2) * BK, (t + 2) % NSTAGE, tid);

        const uint32_t stbase = sb + stg * STG_B;
        const uint32_t abase = stbase + afoff;
        const uint32_t bbase = stbase + bfoff;

#pragma unroll
        for (int kk = 0; kk < 4; kk++) {
            const uint32_t ko = (uint32_t)(kk * 32);
            uint32_t a[2][4];
            LDSM_X4(a[0][0], a[0][1], a[0][2], a[0][3], abase + ko);
            LDSM_X4(a[1][0], a[1][1], a[1][2], a[1][3],
                    abase + (uint32_t)(16 * ROWB) + ko);
            uint32_t b[8][2];
#pragma unroll
            for (int n2 = 0; n2 < 4; n2++)
                LDSM_X4(b[2 * n2][0], b[2 * n2][1],
                        b[2 * n2 + 1][0], b[2 * n2 + 1][1],
                        bbase + (uint32_t)(n2 * 16 * ROWB) + ko);
#pragma unroll
            for (int mb = 0; mb < 2; mb++)
#pragma unroll
                for (int nb = 0; nb < 8; nb++)
                    MMA_F16(d[mb][nb], a[mb][0], a[mb][1], a[mb][2], a[mb][3],
                            b[nb][0], b[nb][1]);
        }
    }

    // epilogue: accumulate partial sums into C (RED.F32; C pre-zeroed)
#pragma unroll
    for (int mb = 0; mb < 2; mb++) {
        int row0 = bm0 + m0 + mb * 16 + q;
#pragma unroll
        for (int nb = 0; nb < 8; nb++) {
            int col = bn0 + n0 + nb * 8 + 2 * cl;
            float* p0 = C + (size_t)row0 * OUT_F + col;
            atomicAdd(p0,     d[mb][nb][0]);
            atomicAdd(p0 + 1, d[mb][nb][1]);
            float* p1 = C + (size_t)(row0 + 8) * OUT_F + col;
            atomicAdd(p1,     d[mb][nb][2]);
            atomicAdd(p1 + 1, d[mb][nb][3]);
        }
    }
}

// ---------------------------------------------------------------------------
// Launch. Inputs: x, base_weight, spline_weight, spline_scaler, grid
// ---------------------------------------------------------------------------
extern "C" void kernel_launch(void* const* d_in, const int* in_sizes, int n_in,
                              void* d_out, int out_size) {
    (void)in_sizes; (void)n_in; (void)out_size;
    const float* x  = (const float*)d_in[0];
    const float* bw = (const float*)d_in[1];
    const float* sw = (const float*)d_in[2];
    const float* sc = (const float*)d_in[3];
    float* out = (float*)d_out;

    cudaFuncSetAttribute(kan_gemm, cudaFuncAttributeMaxDynamicSharedMemorySize,
                         SMEM_TOTAL);

    kan_prep<<<dim3(ZB + NZBLK, IN_F / 256), 256>>>(x, bw, sw, sc, out);
    kan_gemm<<<(BATCH / BM) * (OUT_F / BN) * KSPLIT, NTHREADS, SMEM_TOTAL>>>(out);
}

// round 16
// speedup vs baseline: 1.1202x; 1.1202x over previous
#include <cuda_runtime.h>
#include <cuda_fp16.h>
#include <cstdint>
#include <cstddef>

#define IN_F   1024
#define OUT_F  1024
#define BATCH  8192
#define NFEAT  7
#define KTOT   (IN_F * NFEAT)   // 7168

// ---------------------------------------------------------------------------
// Scratch: fp16 operands. g_A: [b][k] row-major. g_W: [o][k].
// ---------------------------------------------------------------------------
__device__ __align__(256) __half g_A[(size_t)BATCH * KTOT];
__device__ __align__(256) __half g_W[(size_t)OUT_F * KTOT];

// ---------------------------------------------------------------------------
// Helpers
// ---------------------------------------------------------------------------
__device__ __forceinline__ unsigned smem_u32(const void* p) {
    return (unsigned)__cvta_generic_to_shared(p);
}
#define CP_ASYNC16(dst_u32, src_ptr) \
    asm volatile("cp.async.cg.shared.global [%0], [%1], 16;\n" :: "r"(dst_u32), "l"(src_ptr))
#define CP_COMMIT() asm volatile("cp.async.commit_group;\n")
#define CP_WAIT(n)  asm volatile("cp.async.wait_group %0;\n" :: "n"(n))

#define LDSM_X4(r0, r1, r2, r3, addr) \
    asm volatile("ldmatrix.sync.aligned.m8n8.x4.shared.b16 {%0,%1,%2,%3}, [%4];" \
                 : "=r"(r0), "=r"(r1), "=r"(r2), "=r"(r3) : "r"(addr))

#define MMA_F16(d, a0, a1, a2, a3, b0, b1) \
    asm volatile( \
        "mma.sync.aligned.m16n8k16.row.col.f32.f16.f16.f32 " \
        "{%0,%1,%2,%3}, {%4,%5,%6,%7}, {%8,%9}, {%0,%1,%2,%3};" \
        : "+f"((d)[0]), "+f"((d)[1]), "+f"((d)[2]), "+f"((d)[3]) \
        : "r"(a0), "r"(a1), "r"(a2), "r"(a3), "r"(b0), "r"(b1))

// ---------------------------------------------------------------------------
// Schedule constants
// ---------------------------------------------------------------------------
#define NSM 148
#define NTILES 256               // 64 bm x 4 bn
#define NFULL NSM                // tiles 0..147: full-K, one wave
#define NSPLITT (NTILES - NFULL) // 108 tiles split K x 4
#define KSPLIT 4
#define SPLIT_ROW0 ((NFULL / 4) * 128)   // bm>=37 -> rows 4736+ need zeroed C

// ---------------------------------------------------------------------------
// Kernel 1: combined prep (one launch, three independent grid partitions).
//   bx <  BATCH              : features for batch row bx -> g_A
//   BATCH <= bx < BATCH+OUT_F: combined weights -> g_W
//   bx >= ZB                 : zero C rows [4736, 8192) (split-K region)
// ---------------------------------------------------------------------------
#define ZB (BATCH + OUT_F)
#define NZBLK 108                // 108 x 4 x 8192 floats = 3456 rows

__global__ void kan_prep(const float* __restrict__ x,
                         const float* __restrict__ bw,
                         const float* __restrict__ sw,
                         const float* __restrict__ sc,
                         float* __restrict__ C) {
    int bx = blockIdx.x;
    int tid = threadIdx.x;

    if (bx >= ZB) {
        size_t off = (size_t)SPLIT_ROW0 * OUT_F
                   + ((size_t)(bx - ZB) * 4 + blockIdx.y) * 8192;
        float4* p = (float4*)(C + off);
        const float4 z = make_float4(0.f, 0.f, 0.f, 0.f);
#pragma unroll
        for (int r = 0; r < 8; r++) p[tid + r * 256] = z;
        return;
    }

    __shared__ __half sbuf[256 * NFEAT];
    int i = blockIdx.y * 256 + tid;
    float vals[NFEAT];

    if (bx < BATCH) {
        float xv = x[(size_t)bx * IN_F + i];
        float tt = xv * xv;
        float P = fmaf(tt, fmaf(tt, fmaf(tt, -2.10813e-4f, 2.08333333e-3f),
                                -2.08333333e-2f), 0.25f);
        vals[0] = xv * fmaf(xv, P, 0.5f);
        float u  = (xv + 1.0f) * 1.5f;
        int idx  = (int)floorf(u);
        idx = idx < 0 ? 0 : (idx > 2 ? 2 : idx);
        float t  = u - (float)idx;
        float t2 = t * t, t3 = t2 * t;
        float omt = 1.0f - t;
        const float c6 = 1.0f / 6.0f;
        float v0 = omt * omt * omt * c6;
        float v1 = (3.0f * t3 - 6.0f * t2 + 4.0f) * c6;
        float v2 = (-3.0f * t3 + 3.0f * t2 + 3.0f * t + 1.0f) * c6;
        float v3 = t3 * c6;
        vals[1] = (idx == 0) ? v0 : 0.0f;
        vals[2] = (idx == 0) ? v1 : ((idx == 1) ? v0 : 0.0f);
        vals[3] = (idx == 0) ? v2 : ((idx == 1) ? v1 : v0);
        vals[4] = (idx == 0) ? v3 : ((idx == 1) ? v2 : v1);
        vals[5] = (idx == 1) ? v3 : ((idx == 2) ? v2 : 0.0f);
        vals[6] = (idx == 2) ? v3 : 0.0f;
    } else {
        int o = bx - BATCH;
        size_t oi = (size_t)o * IN_F + i;
        float s = sc[oi];
        vals[0] = bw[oi];
        const float* swp = sw + oi * 6;
#pragma unroll
        for (int n = 0; n < 6; n++) vals[n + 1] = swp[n] * s;
    }

#pragma unroll
    for (int j = 0; j < NFEAT; j++)
        sbuf[tid * NFEAT + j] = __float2half_rn(vals[j]);
    __syncthreads();

    __half* gdst = (bx < BATCH) ? (g_A + (size_t)bx * KTOT)
                                : (g_W + (size_t)(bx - BATCH) * KTOT);
    float4* dst = (float4*)(gdst + (size_t)blockIdx.y * (256 * NFEAT));
    if (tid < 224) dst[tid] = ((const float4*)sbuf)[tid];
}

// ---------------------------------------------------------------------------
// Kernel 2: fp16 mma.sync GEMM, HYBRID schedule vs wave quantization.
//   bids 0..147   : tiles 0..147 full-K (112 iters), plain-STG epilogue.
//                   Exactly one wave (1 CTA/SM, smem-limited) -> no tail.
//   bids 148..579 : tiles 148..255 split K x 4 (28-iter units), RED epilogue
//                   into pre-zeroed C. 432 units / 148 SMs = 3 short waves.
// Tile engine (R14, best known): 128x256 CTA, 512 thr, 16 warps (4M x 4N,
// warp 32x64), BK=64, 144B row stride (conflict-free LDSM), 3-stage ring.
// ---------------------------------------------------------------------------
#define BM 128
#define BN 256
#define BK 64
#define NT_FULL (KTOT / BK)          // 112
#define KCHUNK (KTOT / KSPLIT)       // 1792
#define NT_QTR (KCHUNK / BK)         // 28
#define ROWB 144
#define A_STG_B (BM * ROWB)
#define B_STG_B (BN * ROWB)
#define STG_B (A_STG_B + B_STG_B)
#define NSTAGE 3
#define SMEM_TOTAL (NSTAGE * STG_B)  // 165888 -> 1 CTA/SM
#define NTHREADS 512

__device__ __forceinline__ void load_stage(uint32_t sb, int bm0, int bn0,
                                           int k0, int stg, int tid) {
    uint32_t base = sb + stg * STG_B;
#pragma unroll
    for (int r = 0; r < 2; r++) {
        int c = tid + r * NTHREADS;
        int row = c >> 3, ch = c & 7;
        CP_ASYNC16(base + (uint32_t)(row * ROWB + ch * 16),
                   g_A + (size_t)(bm0 + row) * KTOT + k0 + ch * 8);
    }
    uint32_t bbase = base + A_STG_B;
#pragma unroll
    for (int r = 0; r < 4; r++) {
        int c = tid + r * NTHREADS;
        int row = c >> 3, ch = c & 7;
        CP_ASYNC16(bbase + (uint32_t)(row * ROWB + ch * 16),
                   g_W + (size_t)(bn0 + row) * KTOT + k0 + ch * 8);
    }
    CP_COMMIT();
}

__global__ __launch_bounds__(NTHREADS, 1) void kan_gemm(float* __restrict__ C) {
    extern __shared__ char dsm[];
    uint32_t sb = smem_u32(dsm);
    const int tid = threadIdx.x;
    const int wid = tid >> 5, lane = tid & 31;
    const int q = lane >> 2, cl = lane & 3;

    // hybrid decode: tile = bm*4 + bn (bn fastest -> A sharing)
    const int bid = blockIdx.x;
    int tile, kbase, niter;
    bool full;
    if (bid < NFULL) {
        tile = bid; kbase = 0; niter = NT_FULL; full = true;
    } else {
        int u = bid - NFULL;
        tile = NFULL + (u >> 2);
        kbase = (u & 3) * KCHUNK;
        niter = NT_QTR;
        full = false;
    }
    const int bm0 = (tile >> 2) * BM;
    const int bn0 = (tile & 3) * BN;

    const int m0 = (wid & 3) * 32;
    const int n0 = (wid >> 2) * 64;

    float d[2][8][4];
#pragma unroll
    for (int mb = 0; mb < 2; mb++)
#pragma unroll
        for (int nb = 0; nb < 8; nb++)
#pragma unroll
            for (int r = 0; r < 4; r++) d[mb][nb][r] = 0.0f;

    load_stage(sb, bm0, bn0, kbase, 0, tid);
    load_stage(sb, bm0, bn0, kbase + BK, 1, tid);

    const int r8 = lane & 7, tq = lane >> 3;
    const uint32_t afoff =
        (uint32_t)((m0 + (tq & 1) * 8 + r8) * ROWB + (tq >> 1) * 16);
    const uint32_t bfoff =
        (uint32_t)(A_STG_B + (n0 + (tq >> 1) * 8 + r8) * ROWB + (tq & 1) * 16);

    for (int t = 0; t < niter; t++) {
        const int stg = t % NSTAGE;
        CP_WAIT(1);
        __syncthreads();
        if (t + 2 < niter)
            load_stage(sb, bm0, bn0, kbase + (t + 2) * BK, (t + 2) % NSTAGE, tid);

        const uint32_t stbase = sb + stg * STG_B;
        const uint32_t abase = stbase + afoff;
        const uint32_t bbase = stbase + bfoff;

#pragma unroll
        for (int kk = 0; kk < 4; kk++) {
            const uint32_t ko = (uint32_t)(kk * 32);
            uint32_t a[2][4];
            LDSM_X4(a[0][0], a[0][1], a[0][2], a[0][3], abase + ko);
            LDSM_X4(a[1][0], a[1][1], a[1][2], a[1][3],
                    abase + (uint32_t)(16 * ROWB) + ko);
            uint32_t b[8][2];
#pragma unroll
            for (int n2 = 0; n2 < 4; n2++)
                LDSM_X4(b[2 * n2][0], b[2 * n2][1],
                        b[2 * n2 + 1][0], b[2 * n2 + 1][1],
                        bbase + (uint32_t)(n2 * 16 * ROWB) + ko);
#pragma unroll
            for (int mb = 0; mb < 2; mb++)
#pragma unroll
                for (int nb = 0; nb < 8; nb++)
                    MMA_F16(d[mb][nb], a[mb][0], a[mb][1], a[mb][2], a[mb][3],
                            b[nb][0], b[nb][1]);
        }
    }

    // epilogue: full tiles store, split units accumulate (C pre-zeroed there)
#pragma unroll
    for (int mb = 0; mb < 2; mb++) {
        int row0 = bm0 + m0 + mb * 16 + q;
#pragma unroll
        for (int nb = 0; nb < 8; nb++) {
            int col = bn0 + n0 + nb * 8 + 2 * cl;
            float* p0 = C + (size_t)row0 * OUT_F + col;
            float* p1 = C + (size_t)(row0 + 8) * OUT_F + col;
            if (full) {
                *(float2*)p0 = make_float2(d[mb][nb][0], d[mb][nb][1]);
                *(float2*)p1 = make_float2(d[mb][nb][2], d[mb][nb][3]);
            } else {
                atomicAdd(p0,     d[mb][nb][0]);
                atomicAdd(p0 + 1, d[mb][nb][1]);
                atomicAdd(p1,     d[mb][nb][2]);
                atomicAdd(p1 + 1, d[mb][nb][3]);
            }
        }
    }
}

// ---------------------------------------------------------------------------
// Launch. Inputs: x, base_weight, spline_weight, spline_scaler, grid
// ---------------------------------------------------------------------------
extern "C" void kernel_launch(void* const* d_in, const int* in_sizes, int n_in,
                              void* d_out, int out_size) {
    (void)in_sizes; (void)n_in; (void)out_size;
    const float* x  = (const float*)d_in[0];
    const float* bw = (const float*)d_in[1];
    const float* sw = (const float*)d_in[2];
    const float* sc = (const float*)d_in[3];
    float* out = (float*)d_out;

    cudaFuncSetAttribute(kan_gemm, cudaFuncAttributeMaxDynamicSharedMemorySize,
                         SMEM_TOTAL);

    kan_prep<<<dim3(ZB + NZBLK, IN_F / 256), 256>>>(x, bw, sw, sc, out);
    kan_gemm<<<NFULL + NSPLITT * KSPLIT, NTHREADS, SMEM_TOTAL>>>(out);
}

// round 17
// speedup vs baseline: 1.1502x; 1.0268x over previous
#include <cuda_runtime.h>
#include <cuda_fp16.h>
#include <cstdint>
#include <cstddef>

#define IN_F   1024
#define OUT_F  1024
#define BATCH  8192
#define NFEAT  7
#define KTOT   (IN_F * NFEAT)   // 7168

// ---------------------------------------------------------------------------
// Scratch: fp16 operands. g_A: [b][k] row-major. g_W: [o][k].
// ---------------------------------------------------------------------------
__device__ __align__(256) __half g_A[(size_t)BATCH * KTOT];
__device__ __align__(256) __half g_W[(size_t)OUT_F * KTOT];

// ---------------------------------------------------------------------------
// Helpers
// ---------------------------------------------------------------------------
__device__ __forceinline__ unsigned smem_u32(const void* p) {
    return (unsigned)__cvta_generic_to_shared(p);
}
#define CP_ASYNC16(dst_u32, src_ptr) \
    asm volatile("cp.async.cg.shared.global [%0], [%1], 16;\n" :: "r"(dst_u32), "l"(src_ptr))
#define CP_COMMIT() asm volatile("cp.async.commit_group;\n")
#define CP_WAIT(n)  asm volatile("cp.async.wait_group %0;\n" :: "n"(n))

#define LDSM_X4(r0, r1, r2, r3, addr) \
    asm volatile("ldmatrix.sync.aligned.m8n8.x4.shared.b16 {%0,%1,%2,%3}, [%4];" \
                 : "=r"(r0), "=r"(r1), "=r"(r2), "=r"(r3) : "r"(addr))

#define MMA_F16(d, a0, a1, a2, a3, b0, b1) \
    asm volatile( \
        "mma.sync.aligned.m16n8k16.row.col.f32.f16.f16.f32 " \
        "{%0,%1,%2,%3}, {%4,%5,%6,%7}, {%8,%9}, {%0,%1,%2,%3};" \
        : "+f"((d)[0]), "+f"((d)[1]), "+f"((d)[2]), "+f"((d)[3]) \
        : "r"(a0), "r"(a1), "r"(a2), "r"(a3), "r"(b0), "r"(b1))

// ---------------------------------------------------------------------------
// Schedule constants (hybrid: proven in R16)
// ---------------------------------------------------------------------------
#define NSM 148
#define NTILES 256               // 64 bm x 4 bn
#define NFULL NSM                // tiles 0..147: full-K, exactly one wave
#define NSPLITT (NTILES - NFULL) // 108 tiles split K x 4
#define KSPLIT 4
#define SPLIT_ROW0 ((NFULL / 4) * 128)   // rows 4736+ need zeroed C

// ---------------------------------------------------------------------------
// Kernel 1: combined prep (three independent grid partitions).
//   bx <  BATCH              : features for batch row bx -> g_A
//   BATCH <= bx < BATCH+OUT_F: combined weights -> g_W
//   bx >= ZB                 : zero C rows [4736, 8192) (split-K region)
// ---------------------------------------------------------------------------
#define ZB (BATCH + OUT_F)
#define NZBLK 108

__global__ void kan_prep(const float* __restrict__ x,
                         const float* __restrict__ bw,
                         const float* __restrict__ sw,
                         const float* __restrict__ sc,
                         float* __restrict__ C) {
    int bx = blockIdx.x;
    int tid = threadIdx.x;

    if (bx >= ZB) {
        size_t off = (size_t)SPLIT_ROW0 * OUT_F
                   + ((size_t)(bx - ZB) * 4 + blockIdx.y) * 8192;
        float4* p = (float4*)(C + off);
        const float4 z = make_float4(0.f, 0.f, 0.f, 0.f);
#pragma unroll
        for (int r = 0; r < 8; r++) p[tid + r * 256] = z;
        return;
    }

    __shared__ __half sbuf[256 * NFEAT];
    int i = blockIdx.y * 256 + tid;
    float vals[NFEAT];

    if (bx < BATCH) {
        float xv = x[(size_t)bx * IN_F + i];
        float tt = xv * xv;
        float P = fmaf(tt, fmaf(tt, fmaf(tt, -2.10813e-4f, 2.08333333e-3f),
                                -2.08333333e-2f), 0.25f);
        vals[0] = xv * fmaf(xv, P, 0.5f);
        float u  = (xv + 1.0f) * 1.5f;
        int idx  = (int)floorf(u);
        idx = idx < 0 ? 0 : (idx > 2 ? 2 : idx);
        float t  = u - (float)idx;
        float t2 = t * t, t3 = t2 * t;
        float omt = 1.0f - t;
        const float c6 = 1.0f / 6.0f;
        float v0 = omt * omt * omt * c6;
        float v1 = (3.0f * t3 - 6.0f * t2 + 4.0f) * c6;
        float v2 = (-3.0f * t3 + 3.0f * t2 + 3.0f * t + 1.0f) * c6;
        float v3 = t3 * c6;
        vals[1] = (idx == 0) ? v0 : 0.0f;
        vals[2] = (idx == 0) ? v1 : ((idx == 1) ? v0 : 0.0f);
        vals[3] = (idx == 0) ? v2 : ((idx == 1) ? v1 : v0);
        vals[4] = (idx == 0) ? v3 : ((idx == 1) ? v2 : v1);
        vals[5] = (idx == 1) ? v3 : ((idx == 2) ? v2 : 0.0f);
        vals[6] = (idx == 2) ? v3 : 0.0f;
    } else {
        int o = bx - BATCH;
        size_t oi = (size_t)o * IN_F + i;
        float s = sc[oi];
        vals[0] = bw[oi];
        const float* swp = sw + oi * 6;
#pragma unroll
        for (int n = 0; n < 6; n++) vals[n + 1] = swp[n] * s;
    }

#pragma unroll
    for (int j = 0; j < NFEAT; j++)
        sbuf[tid * NFEAT + j] = __float2half_rn(vals[j]);
    __syncthreads();

    __half* gdst = (bx < BATCH) ? (g_A + (size_t)bx * KTOT)
                                : (g_W + (size_t)(bx - BATCH) * KTOT);
    float4* dst = (float4*)(gdst + (size_t)blockIdx.y * (256 * NFEAT));
    if (tid < 224) dst[tid] = ((const float4*)sbuf)[tid];
}

// ---------------------------------------------------------------------------
// Kernel 2: fp16 mma.sync GEMM, hybrid schedule, BK=128 (halved iter count:
// 56 full / 14 per split unit) to amortize per-iteration overhead
// (barrier + wait + addressing). 2-stage ring, prefetch distance 1
// (load ~600cyc << ~6900cyc compute/iter). 272B rows keep the conflict-free
// LDSM bank pattern (272 = 144 mod 32 banks).
//   bids 0..147   : full-K tiles, STG epilogue, exactly one wave.
//   bids 148..579 : 108 tiles split K x 4, RED epilogue into pre-zeroed C.
// ---------------------------------------------------------------------------
#define BM 128
#define BN 256
#define BK 128
#define NT_FULL (KTOT / BK)          // 56
#define KCHUNK (KTOT / KSPLIT)       // 1792
#define NT_QTR (KCHUNK / BK)         // 14
#define ROWB 272                     // 256 data + 16 pad
#define A_STG_B (BM * ROWB)          // 34816
#define B_STG_B (BN * ROWB)          // 69632
#define STG_B (A_STG_B + B_STG_B)    // 104448
#define NSTAGE 2
#define SMEM_TOTAL (NSTAGE * STG_B)  // 208896 -> 1 CTA/SM
#define NTHREADS 512

__device__ __forceinline__ void load_stage(uint32_t sb, int bm0, int bn0,
                                           int k0, int stg, int tid) {
    uint32_t base = sb + stg * STG_B;
    // A: 128 rows x 16 chunks of 16B = 2048 chunks (4/thread)
#pragma unroll
    for (int r = 0; r < 4; r++) {
        int c = tid + r * NTHREADS;
        int row = c >> 4, ch = c & 15;
        CP_ASYNC16(base + (uint32_t)(row * ROWB + ch * 16),
                   g_A + (size_t)(bm0 + row) * KTOT + k0 + ch * 8);
    }
    // B: 256 rows x 16 chunks = 4096 chunks (8/thread)
    uint32_t bbase = base + A_STG_B;
#pragma unroll
    for (int r = 0; r < 8; r++) {
        int c = tid + r * NTHREADS;
        int row = c >> 4, ch = c & 15;
        CP_ASYNC16(bbase + (uint32_t)(row * ROWB + ch * 16),
                   g_W + (size_t)(bn0 + row) * KTOT + k0 + ch * 8);
    }
    CP_COMMIT();
}

__global__ __launch_bounds__(NTHREADS, 1) void kan_gemm(float* __restrict__ C) {
    extern __shared__ char dsm[];
    uint32_t sb = smem_u32(dsm);
    const int tid = threadIdx.x;
    const int wid = tid >> 5, lane = tid & 31;
    const int q = lane >> 2, cl = lane & 3;

    // hybrid decode: tile = bm*4 + bn (bn fastest -> A sharing)
    const int bid = blockIdx.x;
    int tile, kbase, niter;
    bool full;
    if (bid < NFULL) {
        tile = bid; kbase = 0; niter = NT_FULL; full = true;
    } else {
        int u = bid - NFULL;
        tile = NFULL + (u >> 2);
        kbase = (u & 3) * KCHUNK;
        niter = NT_QTR;
        full = false;
    }
    const int bm0 = (tile >> 2) * BM;
    const int bn0 = (tile & 3) * BN;

    const int m0 = (wid & 3) * 32;
    const int n0 = (wid >> 2) * 64;

    float d[2][8][4];
#pragma unroll
    for (int mb = 0; mb < 2; mb++)
#pragma unroll
        for (int nb = 0; nb < 8; nb++)
#pragma unroll
            for (int r = 0; r < 4; r++) d[mb][nb][r] = 0.0f;

    load_stage(sb, bm0, bn0, kbase, 0, tid);

    const int r8 = lane & 7, tq = lane >> 3;
    const uint32_t afoff =
        (uint32_t)((m0 + (tq & 1) * 8 + r8) * ROWB + (tq >> 1) * 16);
    const uint32_t bfoff =
        (uint32_t)(A_STG_B + (n0 + (tq >> 1) * 8 + r8) * ROWB + (tq & 1) * 16);

    for (int t = 0; t < niter; t++) {
        const int stg = t & 1;
        CP_WAIT(0);        // stage t arrived (issued one compute-iter ago)
        __syncthreads();   // + all warps done reading stage t-1
        if (t + 1 < niter)
            load_stage(sb, bm0, bn0, kbase + (t + 1) * BK, stg ^ 1, tid);

        const uint32_t stbase = sb + stg * STG_B;
        const uint32_t abase = stbase + afoff;
        const uint32_t bbase = stbase + bfoff;

#pragma unroll
        for (int kk = 0; kk < 8; kk++) {   // 8 x k16 per BK=128
            const uint32_t ko = (uint32_t)(kk * 32);
            uint32_t a[2][4];
            LDSM_X4(a[0][0], a[0][1], a[0][2], a[0][3], abase + ko);
            LDSM_X4(a[1][0], a[1][1], a[1][2], a[1][3],
                    abase + (uint32_t)(16 * ROWB) + ko);
            uint32_t b[8][2];
#pragma unroll
            for (int n2 = 0; n2 < 4; n2++)
                LDSM_X4(b[2 * n2][0], b[2 * n2][1],
                        b[2 * n2 + 1][0], b[2 * n2 + 1][1],
                        bbase + (uint32_t)(n2 * 16 * ROWB) + ko);
#pragma unroll
            for (int mb = 0; mb < 2; mb++)
#pragma unroll
                for (int nb = 0; nb < 8; nb++)
                    MMA_F16(d[mb][nb], a[mb][0], a[mb][1], a[mb][2], a[mb][3],
                            b[nb][0], b[nb][1]);
        }
    }

    // epilogue: full tiles store, split units accumulate (C pre-zeroed there)
#pragma unroll
    for (int mb = 0; mb < 2; mb++) {
        int row0 = bm0 + m0 + mb * 16 + q;
#pragma unroll
        for (int nb = 0; nb < 8; nb++) {
            int col = bn0 + n0 + nb * 8 + 2 * cl;
            float* p0 = C + (size_t)row0 * OUT_F + col;
            float* p1 = C + (size_t)(row0 + 8) * OUT_F + col;
            if (full) {
                *(float2*)p0 = make_float2(d[mb][nb][0], d[mb][nb][1]);
                *(float2*)p1 = make_float2(d[mb][nb][2], d[mb][nb][3]);
            } else {
                atomicAdd(p0,     d[mb][nb][0]);
                atomicAdd(p0 + 1, d[mb][nb][1]);
                atomicAdd(p1,     d[mb][nb][2]);
                atomicAdd(p1 + 1, d[mb][nb][3]);
            }
        }
    }
}

// ---------------------------------------------------------------------------
// Launch. Inputs: x, base_weight, spline_weight, spline_scaler, grid
// ---------------------------------------------------------------------------
extern "C" void kernel_launch(void* const* d_in, const int* in_sizes, int n_in,
                              void* d_out, int out_size) {
    (void)in_sizes; (void)n_in; (void)out_size;
    const float* x  = (const float*)d_in[0];
    const float* bw = (const float*)d_in[1];
    const float* sw = (const float*)d_in[2];
    const float* sc = (const float*)d_in[3];
    float* out = (float*)d_out;

    cudaFuncSetAttribute(kan_gemm, cudaFuncAttributeMaxDynamicSharedMemorySize,
                         SMEM_TOTAL);

    kan_prep<<<dim3(ZB + NZBLK, IN_F / 256), 256>>>(x, bw, sw, sc, out);
    kan_gemm<<<NFULL + NSPLITT * KSPLIT, NTHREADS, SMEM_TOTAL>>>(out);
}